// round 1
// baseline (speedup 1.0000x reference)
#include <cuda_runtime.h>
#include <cstdint>

#define N_NODES 20000
#define N_EDGES 320000
#define F_IN    128
#define HID     128
#define NHEAD   4
#define HD      512   // NHEAD*HID

// ---------------- scratch (device globals; no allocation allowed) -----------
__device__ float g_feat[N_NODES * HD];
__device__ float g_res [N_NODES * HD];
__device__ float g_rst [N_NODES * HD];
__device__ float g_h1  [N_NODES * HID];
__device__ float g_h2  [N_NODES * HID];
__device__ float g_el  [N_NODES * NHEAD];
__device__ float g_er  [N_NODES * NHEAD];
__device__ int   g_deg [N_NODES];
__device__ int   g_cnt [N_NODES];
__device__ int   g_off [N_NODES + 1];
__device__ int   g_ssrc[N_EDGES];

// ---------------- CSR build -------------------------------------------------
__global__ void zero_counts_kernel() {
    int i = blockIdx.x * blockDim.x + threadIdx.x;
    if (i < N_NODES) { g_deg[i] = 0; g_cnt[i] = 0; }
}

__global__ void count_kernel(const int* __restrict__ dst) {
    int e = blockIdx.x * blockDim.x + threadIdx.x;
    if (e < N_EDGES) atomicAdd(&g_deg[dst[e]], 1);
}

__global__ void scan_kernel() {
    __shared__ int sh[1024];
    __shared__ int carry;
    int tid = threadIdx.x;
    if (tid == 0) { carry = 0; g_off[0] = 0; }
    __syncthreads();
    for (int base = 0; base < N_NODES; base += 1024) {
        int i = base + tid;
        int v = (i < N_NODES) ? g_deg[i] : 0;
        sh[tid] = v;
        __syncthreads();
        for (int s = 1; s < 1024; s <<= 1) {
            int t = (tid >= s) ? sh[tid - s] : 0;
            __syncthreads();
            sh[tid] += t;
            __syncthreads();
        }
        if (i < N_NODES) g_off[i + 1] = sh[tid] + carry;
        __syncthreads();
        if (tid == 0) carry += sh[1023];
        __syncthreads();
    }
}

__global__ void fill_kernel(const int* __restrict__ src, const int* __restrict__ dst) {
    int e = blockIdx.x * blockDim.x + threadIdx.x;
    if (e < N_EDGES) {
        int d = dst[e];
        int p = g_off[d] + atomicAdd(&g_cnt[d], 1);
        g_ssrc[p] = src[e];
    }
}

// ---------------- fp32 tiled GEMM: C[M,Nc] = A[M,K] @ B[K,Nc] (+bias,relu) --
template <bool RELU, bool HASBIAS>
__global__ void gemm_kernel(const float* __restrict__ A, const float* __restrict__ B,
                            const float* __restrict__ bias, float* __restrict__ C,
                            int M, int Nc, int K) {
    constexpr int BM = 64, BN = 64, BK = 16;
    __shared__ float As[BK][BM + 4];
    __shared__ float Bs[BK][BN];
    int tid = threadIdx.x;                 // 256 threads
    int bm = blockIdx.y * BM, bn = blockIdx.x * BN;
    int tx = tid & 15, ty = tid >> 4;

    int am = tid >> 2;                     // 0..63
    int ak = (tid & 3) << 2;               // 0,4,8,12
    int bk = (tid * 4) >> 6;               // 0..15
    int bn_i = (tid * 4) & 63;

    float acc[4][4] = {};

    for (int k0 = 0; k0 < K; k0 += BK) {
        int arow = bm + am;
        float4 av = make_float4(0.f, 0.f, 0.f, 0.f);
        if (arow < M) av = *(const float4*)(A + (size_t)arow * K + k0 + ak);
        As[ak + 0][am] = av.x; As[ak + 1][am] = av.y;
        As[ak + 2][am] = av.z; As[ak + 3][am] = av.w;

        float4 bv = *(const float4*)(B + (size_t)(k0 + bk) * Nc + bn + bn_i);
        *(float4*)&Bs[bk][bn_i] = bv;
        __syncthreads();

#pragma unroll
        for (int kk = 0; kk < BK; kk++) {
            float4 a = *(const float4*)&As[kk][ty * 4];
            float4 b = *(const float4*)&Bs[kk][tx * 4];
            float ar[4] = {a.x, a.y, a.z, a.w};
            float br[4] = {b.x, b.y, b.z, b.w};
#pragma unroll
            for (int i = 0; i < 4; i++)
#pragma unroll
                for (int j = 0; j < 4; j++)
                    acc[i][j] += ar[i] * br[j];
        }
        __syncthreads();
    }

#pragma unroll
    for (int i = 0; i < 4; i++) {
        int row = bm + ty * 4 + i;
        if (row >= M) continue;
#pragma unroll
        for (int j = 0; j < 4; j++) {
            int col = bn + tx * 4 + j;
            float v = acc[i][j];
            if (HASBIAS) v += bias[col];
            if (RELU) v = fmaxf(v, 0.f);
            C[(size_t)row * Nc + col] = v;
        }
    }
}

// ---------------- per-node attention logits (el/er) -------------------------
__global__ void elr_kernel(const float* __restrict__ feat,
                           const float* __restrict__ al, const float* __restrict__ ar) {
    int w = (blockIdx.x * blockDim.x + threadIdx.x) >> 5;
    if (w >= N_NODES * NHEAD) return;
    int lane = threadIdx.x & 31;
    int n = w >> 2, h = w & 3;
    const float* f = feat + (size_t)n * HD + h * HID;
    float sl = 0.f, sr = 0.f;
#pragma unroll
    for (int i = 0; i < 4; i++) {
        float fv = f[lane + 32 * i];
        sl += fv * al[h * HID + lane + 32 * i];
        sr += fv * ar[h * HID + lane + 32 * i];
    }
#pragma unroll
    for (int s = 16; s; s >>= 1) {
        sl += __shfl_xor_sync(0xffffffffu, sl, s);
        sr += __shfl_xor_sync(0xffffffffu, sr, s);
    }
    if (lane == 0) { g_el[n * NHEAD + h] = sl; g_er[n * NHEAD + h] = sr; }
}

// ------- per-(dst,head) warp: softmax over incoming edges + aggregate -------
__global__ void agg_kernel(const float* __restrict__ feat, const float* __restrict__ res,
                           const float* __restrict__ bias, float* __restrict__ rst) {
    int w = (blockIdx.x * blockDim.x + threadIdx.x) >> 5;
    if (w >= N_NODES * NHEAD) return;
    int lane = threadIdx.x & 31;
    int n = w >> 2, h = w & 3;
    int beg = g_off[n], end = g_off[n + 1];
    float ern = g_er[n * NHEAD + h];

    // pass 1: max logit
    float m = -1e30f;
    for (int k = beg + lane; k < end; k += 32) {
        int s = g_ssrc[k];
        float ev = g_el[s * NHEAD + h] + ern;
        ev = ev > 0.f ? ev : 0.2f * ev;
        m = fmaxf(m, ev);
    }
#pragma unroll
    for (int s = 16; s; s >>= 1) m = fmaxf(m, __shfl_xor_sync(0xffffffffu, m, s));

    // pass 2: sum of exp
    float ssum = 0.f;
    for (int k = beg + lane; k < end; k += 32) {
        int s = g_ssrc[k];
        float ev = g_el[s * NHEAD + h] + ern;
        ev = ev > 0.f ? ev : 0.2f * ev;
        ssum += __expf(ev - m);
    }
#pragma unroll
    for (int s = 16; s; s >>= 1) ssum += __shfl_xor_sync(0xffffffffu, ssum, s);
    float inv = ssum > 0.f ? 1.f / ssum : 0.f;

    // pass 3: weighted gather-accumulate
    float acc0 = 0.f, acc1 = 0.f, acc2 = 0.f, acc3 = 0.f;
    for (int k0 = beg; k0 < end; k0 += 32) {
        int kk = k0 + lane;
        float a = 0.f; int sj = 0;
        if (kk < end) {
            sj = g_ssrc[kk];
            float ev = g_el[sj * NHEAD + h] + ern;
            ev = ev > 0.f ? ev : 0.2f * ev;
            a = __expf(ev - m) * inv;
        }
        int cnt = min(32, end - k0);
        for (int j = 0; j < cnt; j++) {
            float aj = __shfl_sync(0xffffffffu, a, j);
            int s = __shfl_sync(0xffffffffu, sj, j);
            const float* fr = feat + ((size_t)s * NHEAD + h) * HID;
            acc0 += aj * fr[lane];
            acc1 += aj * fr[lane + 32];
            acc2 += aj * fr[lane + 64];
            acc3 += aj * fr[lane + 96];
        }
    }

    // epilogue: + residual + bias, relu
    size_t base = ((size_t)n * NHEAD + h) * HID;
    const float* bb = bias + h * HID;
    float v;
    v = acc0 + res[base + lane]      + bb[lane];      rst[base + lane]      = fmaxf(v, 0.f);
    v = acc1 + res[base + lane + 32] + bb[lane + 32]; rst[base + lane + 32] = fmaxf(v, 0.f);
    v = acc2 + res[base + lane + 64] + bb[lane + 64]; rst[base + lane + 64] = fmaxf(v, 0.f);
    v = acc3 + res[base + lane + 96] + bb[lane + 96]; rst[base + lane + 96] = fmaxf(v, 0.f);
}

// ---------------- final: head-mean, relu, graph max -------------------------
__global__ void init_out_kernel(float* out) {
    if (threadIdx.x < HID) out[threadIdx.x] = 0.f;
}

__global__ void pool_kernel(const float* __restrict__ rst, float* __restrict__ out) {
    int d = threadIdx.x;           // 0..127
    int n0 = blockIdx.x * 64;
    float mx = 0.f;
    for (int i = 0; i < 64; i++) {
        int n = n0 + i;
        if (n >= N_NODES) break;
        const float* r = rst + (size_t)n * HD;
        float s = (r[d] + r[HID + d] + r[2 * HID + d] + r[3 * HID + d]) * 0.25f;
        mx = fmaxf(mx, s);
    }
    atomicMax((int*)out + d, __float_as_int(mx));   // nonneg floats: int-monotonic
}

// ---------------- host ------------------------------------------------------
extern "C" void kernel_launch(void* const* d_in, const int* in_sizes, int n_in,
                              void* d_out, int out_size) {
    const float* x    = (const float*)d_in[0];
    const int*   src  = (const int*)d_in[1];
    const int*   dst  = (const int*)d_in[2];
    const float* W0   = (const float*)d_in[3];
    const float* al0  = (const float*)d_in[4];
    const float* ar0  = (const float*)d_in[5];
    const float* b0   = (const float*)d_in[6];
    const float* rW0  = (const float*)d_in[7];
    const float* DW0  = (const float*)d_in[8];
    const float* Db0  = (const float*)d_in[9];
    const float* W1   = (const float*)d_in[10];
    const float* al1  = (const float*)d_in[11];
    const float* ar1  = (const float*)d_in[12];
    const float* b1   = (const float*)d_in[13];
    const float* rW1  = (const float*)d_in[14];
    const float* DW1  = (const float*)d_in[15];
    const float* Db1  = (const float*)d_in[16];
    const float* W2   = (const float*)d_in[17];
    const float* al2  = (const float*)d_in[18];
    const float* ar2  = (const float*)d_in[19];
    const float* b2   = (const float*)d_in[20];
    const float* rW2  = (const float*)d_in[21];
    float* out = (float*)d_out;

    float *feat, *res, *rst, *h1, *h2;
    cudaGetSymbolAddress((void**)&feat, g_feat);
    cudaGetSymbolAddress((void**)&res,  g_res);
    cudaGetSymbolAddress((void**)&rst,  g_rst);
    cudaGetSymbolAddress((void**)&h1,   g_h1);
    cudaGetSymbolAddress((void**)&h2,   g_h2);

    const int EB = (N_EDGES + 255) / 256;
    const int NB = (N_NODES + 255) / 256;
    const int WGRID = (N_NODES * NHEAD * 32 + 255) / 256;   // warp per (n,h), 256 thr/blk

    dim3 gemm_tb(256);
    dim3 g_nw(512 / 64, (N_NODES + 63) / 64);   // [N,512] outputs
    dim3 g_nd(128 / 64, (N_NODES + 63) / 64);   // [N,128] outputs

    // CSR build (graph is shared by all 3 layers)
    zero_counts_kernel<<<NB, 256>>>();
    count_kernel<<<EB, 256>>>(dst);
    scan_kernel<<<1, 1024>>>();
    fill_kernel<<<EB, 256>>>(src, dst);

    // ---- layer 0 (F_IN=128 -> H x 128) ----
    gemm_kernel<false, false><<<g_nw, gemm_tb>>>(x, W0,  nullptr, feat, N_NODES, HD, F_IN);
    gemm_kernel<false, false><<<g_nw, gemm_tb>>>(x, rW0, nullptr, res,  N_NODES, HD, F_IN);
    elr_kernel<<<WGRID, 256>>>(feat, al0, ar0);
    agg_kernel<<<WGRID, 256>>>(feat, res, b0, rst);
    gemm_kernel<true, true><<<g_nd, gemm_tb>>>(rst, DW0, Db0, h1, N_NODES, HID, HD);

    // ---- layer 1 (HID -> H x 128) ----
    gemm_kernel<false, false><<<g_nw, gemm_tb>>>(h1, W1,  nullptr, feat, N_NODES, HD, HID);
    gemm_kernel<false, false><<<g_nw, gemm_tb>>>(h1, rW1, nullptr, res,  N_NODES, HD, HID);
    elr_kernel<<<WGRID, 256>>>(feat, al1, ar1);
    agg_kernel<<<WGRID, 256>>>(feat, res, b1, rst);
    gemm_kernel<true, true><<<g_nd, gemm_tb>>>(rst, DW1, Db1, h2, N_NODES, HID, HD);

    // ---- layer 2 (HID -> H x 128) + head mean + graph max ----
    gemm_kernel<false, false><<<g_nw, gemm_tb>>>(h2, W2,  nullptr, feat, N_NODES, HD, HID);
    gemm_kernel<false, false><<<g_nw, gemm_tb>>>(h2, rW2, nullptr, res,  N_NODES, HD, HID);
    elr_kernel<<<WGRID, 256>>>(feat, al2, ar2);
    agg_kernel<<<WGRID, 256>>>(feat, res, b2, rst);

    init_out_kernel<<<1, 128>>>(out);
    pool_kernel<<<(N_NODES + 63) / 64, 128>>>(rst, out);
}